// round 5
// baseline (speedup 1.0000x reference)
#include <cuda_runtime.h>
#include <cuda_bf16.h>
#include <mma.h>
#include <cstdint>

// UpConvBlock: y = ConvTranspose2d(x, w1, k=4, s=2, p=1) + b1
//              out = PAC-3x3(y, guide, w2) + b2
// R5: pac via portable wmma (HMMA) bf16x3 split, fp32 register accumulators.
// tcgen05 is unusable: harness PTX target is compute_103 (no 'a'), which
// rejects tcgen05.ld/st/wait. convt stays the R3 FFMA2 kernel.

#define H1 64
#define W1 64
#define CIN 256
#define CMID 128
#define H2 128
#define W2 128
#define BATCH 4

typedef unsigned long long u64;
typedef unsigned int u32;

using namespace nvcuda;

// ---------------- scalar f32x2 helpers (convt) ----------------
__device__ __forceinline__ u64 pack2(float lo, float hi) {
    u64 r; asm("mov.b64 %0,{%1,%2};" : "=l"(r) : "f"(lo), "f"(hi)); return r;
}
__device__ __forceinline__ void unpack2(u64 v, float& lo, float& hi) {
    asm("mov.b64 {%0,%1},%2;" : "=f"(lo), "=f"(hi) : "l"(v));
}
__device__ __forceinline__ u64 ffma2(u64 a, u64 b, u64 c) {
    u64 d; asm("fma.rn.f32x2 %0,%1,%2,%3;" : "=l"(d) : "l"(a), "l"(b), "l"(c)); return d;
}
__device__ __forceinline__ u32 pack_bf16x2(float lo, float hi) {
    u32 r; asm("cvt.rn.bf16x2.f32 %0, %1, %2;" : "=r"(r) : "f"(hi), "f"(lo)); return r;
}

// ---------------- scratch globals ----------------
__device__ float g_y[BATCH * CMID * H2 * W2];
__device__ float g_wt1[4 * CIN * 4 * CMID];            // convt weights [parity][c][tap][o]
__device__ u32   g_w2h[9 * 128 * 64];                  // pac A hi: [ij][o][c-pair] bf16x2
__device__ u32   g_w2l[9 * 128 * 64];                  // pac A lo

// ---------------------------------------------------------------------------
__global__ void transpose_w1(const float* __restrict__ w1) {
    int idx = blockIdx.x * 256 + threadIdx.x;
    if (idx >= 4 * CIN * 4 * CMID) return;
    int o   = idx & 127;
    int tap = (idx >> 7) & 3;
    int c   = (idx >> 9) & 255;
    int par = idx >> 17;
    int di = par >> 1, dj = par & 1;
    int t = tap >> 1, u = tap & 1;
    g_wt1[idx] = w1[(c * CMID + o) * 16 + (3 - di - 2 * t) * 4 + (3 - dj - 2 * u)];
}

__global__ void transpose_w2bf(const float* __restrict__ w2) {
    int idx = blockIdx.x * 256 + threadIdx.x;          // 9*128*64 = 73728
    if (idx >= 9 * 128 * 64) return;
    int cp = idx & 63;
    int o  = (idx >> 6) & 127;
    int ij = idx >> 13;
    int i = ij / 3, j = ij % 3;
    int c0 = cp * 2;
    float v0 = w2[(c0 * CMID + o) * 9 + (2 - i) * 3 + (2 - j)];
    float v1 = w2[((c0 + 1) * CMID + o) * 9 + (2 - i) * 3 + (2 - j)];
    float h0 = __bfloat162float(__float2bfloat16_rn(v0));
    float h1 = __bfloat162float(__float2bfloat16_rn(v1));
    g_w2h[idx] = pack_bf16x2(v0, v1);
    g_w2l[idx] = pack_bf16x2(v0 - h0, v1 - h1);
}

// ---------------------------------------------------------------------------
// Kernel 1 (R3): conv_transpose, parity decomposition, FFMA2.
// ---------------------------------------------------------------------------
__global__ __launch_bounds__(256, 2) void convt_kernel(const float* __restrict__ x,
                                                       const float* __restrict__ b1) {
    const int KC = 8;
    __shared__ float w_s[KC * 4 * 128];
    __shared__ float x_s[KC][9][12];

    const int bz = blockIdx.z;
    const int b  = bz >> 2;
    const int di = (bz >> 1) & 1;
    const int dj = bz & 1;
    const int i0 = blockIdx.y * 8;
    const int j0 = blockIdx.x * 8;
    const int tid = threadIdx.x;
    const int to  = tid >> 3;
    const int tp  = tid & 7;

    const int ihBase = i0 + (di == 0 ? -1 : 0);
    const int jwBase = j0 + (dj == 0 ? -1 : 0);

    u64 acc[4][4];
#pragma unroll
    for (int a = 0; a < 4; a++)
#pragma unroll
        for (int q = 0; q < 4; q++) acc[a][q] = 0ull;

    const float* xb = x + b * (CIN * H1 * W1);
    const float* wt = g_wt1 + (bz & 3) * (CIN * 4 * CMID);

    for (int c0 = 0; c0 < CIN; c0 += KC) {
        for (int idx = tid; idx < KC * 81; idx += 256) {
            int c = idx / 81;
            int r = (idx % 81) / 9;
            int col = idx % 9;
            int gi = ihBase + r;
            int gj = jwBase + col;
            float v = 0.f;
            if ((unsigned)gi < (unsigned)H1 && (unsigned)gj < (unsigned)W1)
                v = xb[(c0 + c) * (H1 * W1) + gi * W1 + gj];
            x_s[c][r][col] = v;
        }
        {
            const float4* src = (const float4*)(wt + c0 * 4 * CMID);
            float4* dst = (float4*)w_s;
#pragma unroll
            for (int k = 0; k < 4; k++) dst[tid + k * 256] = src[tid + k * 256];
        }
        __syncthreads();

#pragma unroll
        for (int c = 0; c < KC; c++) {
#pragma unroll
            for (int t = 0; t < 2; t++) {
                const float* row = &x_s[c][tp + t][0];
                const u64* rp = (const u64*)row;
                u64 e0 = rp[0], e1 = rp[1], e2 = rp[2], e3 = rp[3];
                float r8 = row[8];
                float f0h, f1l, f1h, f2l, f2h, f3l, f3h, dummy;
                unpack2(e0, dummy, f0h);
                unpack2(e1, f1l, f1h);
                unpack2(e2, f2l, f2h);
                unpack2(e3, f3l, f3h);
                u64 s0 = pack2(f0h, f1l);
                u64 s1 = pack2(f1h, f2l);
                u64 s2 = pack2(f2h, f3l);
                u64 s3 = pack2(f3h, r8);
#pragma unroll
                for (int u = 0; u < 2; u++) {
                    float4 a4 = *(const float4*)&w_s[(c * 4 + t * 2 + u) * 128 + to * 4];
                    u64 wa0 = pack2(a4.x, a4.x);
                    u64 wa1 = pack2(a4.y, a4.y);
                    u64 wa2 = pack2(a4.z, a4.z);
                    u64 wa3 = pack2(a4.w, a4.w);
                    u64 p0 = u ? s0 : e0;
                    u64 p1 = u ? s1 : e1;
                    u64 p2 = u ? s2 : e2;
                    u64 p3 = u ? s3 : e3;
                    acc[0][0] = ffma2(wa0, p0, acc[0][0]);
                    acc[0][1] = ffma2(wa0, p1, acc[0][1]);
                    acc[0][2] = ffma2(wa0, p2, acc[0][2]);
                    acc[0][3] = ffma2(wa0, p3, acc[0][3]);
                    acc[1][0] = ffma2(wa1, p0, acc[1][0]);
                    acc[1][1] = ffma2(wa1, p1, acc[1][1]);
                    acc[1][2] = ffma2(wa1, p2, acc[1][2]);
                    acc[1][3] = ffma2(wa1, p3, acc[1][3]);
                    acc[2][0] = ffma2(wa2, p0, acc[2][0]);
                    acc[2][1] = ffma2(wa2, p1, acc[2][1]);
                    acc[2][2] = ffma2(wa2, p2, acc[2][2]);
                    acc[2][3] = ffma2(wa2, p3, acc[2][3]);
                    acc[3][0] = ffma2(wa3, p0, acc[3][0]);
                    acc[3][1] = ffma2(wa3, p1, acc[3][1]);
                    acc[3][2] = ffma2(wa3, p2, acc[3][2]);
                    acc[3][3] = ffma2(wa3, p3, acc[3][3]);
                }
            }
        }
        __syncthreads();
    }

    const int ho = 2 * (i0 + tp) + di;
#pragma unroll
    for (int a = 0; a < 4; a++) {
        int o = to * 4 + a;
        float bias = __ldg(&b1[o]);
        float* yrow = g_y + ((b * CMID + o) * H2 + ho) * W2;
#pragma unroll
        for (int q = 0; q < 4; q++) {
            float lo, hi;
            unpack2(acc[a][q], lo, hi);
            int wo = 2 * (j0 + 2 * q) + dj;
            yrow[wo]     = lo + bias;
            yrow[wo + 2] = hi + bias;
        }
    }
}

// ---------------------------------------------------------------------------
// Kernel 2: PAC via wmma bf16x3. Block = 128 o x 128 px (8h x 16w).
// 8 warps, warp tile 32o x 64px = 2x4 wmma 16x16x16 tiles.
// smem bf16 matrices, row stride 144 elems (288 B, 32B-aligned rows).
// ---------------------------------------------------------------------------
#define SA 144                              // bf16 row stride (elems)
#define MAT_BYTES (128 * SA * 2)            // 36864
#define OFF_AH 0
#define OFF_AL (MAT_BYTES)
#define OFF_BH (2 * MAT_BYTES)
#define OFF_BL (3 * MAT_BYTES)
#define OFF_KS (4 * MAT_BYTES)              // 147456, fp32 [9][128]
#define PAC_SMEM (OFF_KS + 9 * 128 * 4)     // 152064
#define SF 136                              // fp32 epilogue stride

__global__ __launch_bounds__(256, 1) void pac_wmma(const float* __restrict__ guide,
                                                   const float* __restrict__ b2,
                                                   float* __restrict__ out) {
    extern __shared__ __align__(128) char smem[];
    const int tid = threadIdx.x;
    const int wid = tid >> 5;

    const int b  = blockIdx.z;
    const int h0 = blockIdx.y * 8;
    const int w0 = blockIdx.x * 16;

    float* ks = (float*)(smem + OFF_KS);    // [9][128]
    float* gs = (float*)(smem + OFF_AH);    // overlay: [32][10][18]

    // ---- Phase A: guide kernel k[9][128] ----
    for (int t = tid; t < 1152; t += 256) ks[t] = 0.f;

    for (int cc = 0; cc < CMID; cc += 32) {
        __syncthreads();
        for (int idx = tid; idx < 32 * 180; idx += 256) {
            int c = idx / 180;
            int r = (idx % 180) / 18;
            int col = idx % 18;
            int gh = h0 - 1 + r, gw = w0 - 1 + col;
            float v = 0.f;
            if ((unsigned)gh < (unsigned)H2 && (unsigned)gw < (unsigned)W2)
                v = guide[((b * CMID + cc + c) * H2 + gh) * W2 + gw];
            gs[c * 180 + r * 18 + col] = v;
        }
        __syncthreads();
        for (int idx = tid; idx < 1152; idx += 256) {
            int ij = idx >> 7;
            int n  = idx & 127;
            int i = ij / 3, j = ij % 3;
            int r = n >> 4, cw = n & 15;
            float s = 0.f;
#pragma unroll
            for (int c = 0; c < 32; c++) {
                float d = gs[c * 180 + (r + i) * 18 + (cw + j)] - gs[c * 180 + (r + 1) * 18 + (cw + 1)];
                s += d * d;
            }
            ks[idx] += s;
        }
    }
    __syncthreads();
    for (int t = tid; t < 1152; t += 256) ks[t] = __expf(-0.5f * ks[t]);

    // ---- Phase B: 9 ij stages, bf16x3 wmma ----
    const int mo = (wid & 3) * 32;          // warp o-offset
    const int np = (wid >> 2) * 64;         // warp px-offset

    wmma::fragment<wmma::accumulator, 16, 16, 16, float> acc[2][4];
#pragma unroll
    for (int m = 0; m < 2; m++)
#pragma unroll
        for (int n = 0; n < 4; n++) wmma::fill_fragment(acc[m][n], 0.f);

    const float* yb = g_y + b * (CMID * H2 * W2);

    for (int ij = 0; ij < 9; ij++) {
        const int i = ij / 3, j = ij % 3;
        __syncthreads();   // previous MMA reads done before restaging

        // stage A (pre-split weights): [o][c] bf16, row stride SA
        {
            const u32* wAh = g_w2h + ij * 8192;
            const u32* wAl = g_w2l + ij * 8192;
            for (int p = tid; p < 8192; p += 256) {
                int o = p >> 6;
                int cp = p & 63;
                u32 off = (u32)(o * (SA * 2) + cp * 4);
                *(u32*)(smem + OFF_AH + off) = wAh[p];
                *(u32*)(smem + OFF_AL + off) = wAl[p];
            }
        }
        // stage B = y * k, split hi/lo: [c][px] bf16, row stride SA
        for (int p = tid; p < 8192; p += 256) {
            int c = p >> 6;
            int px0 = (p & 63) * 2;
            int r = px0 >> 4, cw = px0 & 15;
            int h = h0 + r + i - 1;
            int w = w0 + cw + j - 1;
            const float* yp = yb + c * (H2 * W2) + h * W2;
            bool okh = (unsigned)h < (unsigned)H2;
            bool ok0 = okh && (unsigned)w < (unsigned)W2;
            bool ok1 = okh && (unsigned)(w + 1) < (unsigned)W2;
            float v0 = ok0 ? yp[w] * ks[ij * 128 + px0] : 0.f;
            float v1 = ok1 ? yp[w + 1] * ks[ij * 128 + px0 + 1] : 0.f;
            float h0f = __bfloat162float(__float2bfloat16_rn(v0));
            float h1f = __bfloat162float(__float2bfloat16_rn(v1));
            u32 off = (u32)(c * (SA * 2) + px0 * 2);
            *(u32*)(smem + OFF_BH + off) = pack_bf16x2(v0, v1);
            *(u32*)(smem + OFF_BL + off) = pack_bf16x2(v0 - h0f, v1 - h1f);
        }
        __syncthreads();

#pragma unroll
        for (int s = 0; s < 3; s++) {
            const __nv_bfloat16* A = (const __nv_bfloat16*)(smem + (s == 2 ? OFF_AL : OFF_AH));
            const __nv_bfloat16* B = (const __nv_bfloat16*)(smem + (s == 1 ? OFF_BL : OFF_BH));
#pragma unroll
            for (int k0 = 0; k0 < 8; k0++) {
                wmma::fragment<wmma::matrix_a, 16, 16, 16, __nv_bfloat16, wmma::row_major> af[2];
                wmma::fragment<wmma::matrix_b, 16, 16, 16, __nv_bfloat16, wmma::row_major> bf[4];
                wmma::load_matrix_sync(af[0], A + mo * SA + k0 * 16, SA);
                wmma::load_matrix_sync(af[1], A + (mo + 16) * SA + k0 * 16, SA);
#pragma unroll
                for (int n = 0; n < 4; n++)
                    wmma::load_matrix_sync(bf[n], B + (k0 * 16) * SA + np + n * 16, SA);
#pragma unroll
                for (int m = 0; m < 2; m++)
#pragma unroll
                    for (int n = 0; n < 4; n++)
                        wmma::mma_sync(acc[m][n], af[m], bf[n], acc[m][n]);
            }
        }
    }

    // ---- Epilogue: acc -> smem fp32 -> coalesced out ----
    __syncthreads();
    float* fbuf = (float*)(smem + OFF_AH);   // [128][SF], 69632 B (over AH+AL)
#pragma unroll
    for (int m = 0; m < 2; m++)
#pragma unroll
        for (int n = 0; n < 4; n++)
            wmma::store_matrix_sync(fbuf + (mo + m * 16) * SF + np + n * 16,
                                    acc[m][n], SF, wmma::mem_row_major);
    __syncthreads();
    for (int idx = tid; idx < 128 * 128; idx += 256) {
        int o = idx >> 7;
        int n = idx & 127;
        float v = fbuf[o * SF + n] + __ldg(&b2[o]);
        out[((b * CMID + o) * H2 + h0 + (n >> 4)) * W2 + w0 + (n & 15)] = v;
    }
}

extern "C" void kernel_launch(void* const* d_in, const int* in_sizes, int n_in,
                              void* d_out, int out_size) {
    const float* x     = (const float*)d_in[0];
    const float* guide = (const float*)d_in[1];
    const float* w1    = (const float*)d_in[2];
    const float* b1    = (const float*)d_in[3];
    const float* w2    = (const float*)d_in[4];
    const float* b2    = (const float*)d_in[5];
    float* out = (float*)d_out;

    cudaFuncSetAttribute(pac_wmma, cudaFuncAttributeMaxDynamicSharedMemorySize, PAC_SMEM);

    transpose_w1<<<(4 * CIN * 4 * CMID + 255) / 256, 256>>>(w1);
    transpose_w2bf<<<(9 * 128 * 64 + 255) / 256, 256>>>(w2);
    convt_kernel<<<dim3(8, 8, BATCH * 4), 256>>>(x, b1);
    pac_wmma<<<dim3(8, 16, BATCH), 256, PAC_SMEM>>>(guide, b2, out);
}

// round 6
// speedup vs baseline: 1.1804x; 1.1804x over previous
#include <cuda_runtime.h>
#include <cuda_bf16.h>
#include <mma.h>
#include <cstdint>

// UpConvBlock: y = ConvTranspose2d(x, w1, k=4, s=2, p=1) + b1
//              out = PAC-3x3(y, guide, w2) + b2
// R6: both stages as wmma(HMMA) bf16x3-split GEMMs (D = Ah*Bh + Ah*Bl + Al*Bh,
// fp32 accumulators). 128o x 64px tiles, 106KB smem -> 2 CTAs/SM, cp.async
// weight staging from pre-split bf16 hi/lo globals.

#define H1 64
#define W1 64
#define CIN 256
#define CMID 128
#define H2 128
#define W2 128
#define BATCH 4

typedef unsigned long long u64;
typedef unsigned int u32;

using namespace nvcuda;

__device__ __forceinline__ u32 pack_bf16x2(float lo, float hi) {
    u32 r; asm("cvt.rn.bf16x2.f32 %0, %1, %2;" : "=r"(r) : "f"(hi), "f"(lo)); return r;
}
__device__ __forceinline__ u32 smem_u32(const void* p) {
    u32 a; asm("{ .reg .u64 t; cvta.to.shared.u64 t, %1; cvt.u32.u64 %0, t; }" : "=r"(a) : "l"(p));
    return a;
}
__device__ __forceinline__ void cpasync16(u32 dst, const void* src) {
    asm volatile("cp.async.ca.shared.global [%0], [%1], 16;" :: "r"(dst), "l"(src));
}
__device__ __forceinline__ void cpasync_wait() {
    asm volatile("cp.async.commit_group;\n\tcp.async.wait_group 0;" ::: "memory");
}

// ---------------- scratch globals ----------------
__device__ float g_y[BATCH * CMID * H2 * W2];
__device__ __align__(128) u32 g_w1h[4 * 8 * 128 * 64];   // [par][kc][o][cpair] bf16x2 hi
__device__ __align__(128) u32 g_w1l[4 * 8 * 128 * 64];   // lo
__device__ __align__(128) u32 g_w2h[9 * 128 * 64];       // [ij][o][cpair] hi
__device__ __align__(128) u32 g_w2l[9 * 128 * 64];       // lo

// smem layout (both kernels): A stride 136 bf16, B stride 72 bf16
#define SA 136
#define SB 72
#define OFF_AH 0
#define OFF_AL 34816
#define OFF_BH 69632
#define OFF_BL 88064
#define OFF_KS 106496                       // pac only: fp32 [9][64]
#define CONVT_SMEM 106496
#define PAC_SMEM  (106496 + 2304)           // 108800

// ---------------------------------------------------------------------------
// Weight pre-split kernels
// ---------------------------------------------------------------------------
__global__ void split_w1(const float* __restrict__ w1) {
    int idx = blockIdx.x * 256 + threadIdx.x;        // 4*8*128*64 = 262144
    if (idx >= 4 * 8 * 128 * 64) return;
    int cp = idx & 63;
    int o  = (idx >> 6) & 127;
    int kc = (idx >> 13) & 7;
    int par = idx >> 16;
    int di = par >> 1, dj = par & 1;
    int c = kc * 32 + (cp >> 1);
    int tap0 = (cp * 2) & 3;                         // {0,2}
    int t0 = tap0 >> 1, u0 = tap0 & 1;
    int t1 = (tap0 + 1) >> 1, u1 = (tap0 + 1) & 1;
    float v0 = w1[(c * CMID + o) * 16 + (3 - di - 2 * t0) * 4 + (3 - dj - 2 * u0)];
    float v1 = w1[(c * CMID + o) * 16 + (3 - di - 2 * t1) * 4 + (3 - dj - 2 * u1)];
    float h0 = __bfloat162float(__float2bfloat16_rn(v0));
    float h1 = __bfloat162float(__float2bfloat16_rn(v1));
    g_w1h[idx] = pack_bf16x2(v0, v1);
    g_w1l[idx] = pack_bf16x2(v0 - h0, v1 - h1);
}

__global__ void split_w2(const float* __restrict__ w2) {
    int idx = blockIdx.x * 256 + threadIdx.x;        // 9*128*64 = 73728
    if (idx >= 9 * 128 * 64) return;
    int cp = idx & 63;
    int o  = (idx >> 6) & 127;
    int ij = idx >> 13;
    int i = ij / 3, j = ij % 3;
    int c0 = cp * 2;
    float v0 = w2[(c0 * CMID + o) * 9 + (2 - i) * 3 + (2 - j)];
    float v1 = w2[((c0 + 1) * CMID + o) * 9 + (2 - i) * 3 + (2 - j)];
    float h0 = __bfloat162float(__float2bfloat16_rn(v0));
    float h1 = __bfloat162float(__float2bfloat16_rn(v1));
    g_w2h[idx] = pack_bf16x2(v0, v1);
    g_w2l[idx] = pack_bf16x2(v0 - h0, v1 - h1);
}

// ---------------------------------------------------------------------------
// Kernel 1: conv_transpose via parity decomposition, wmma bf16x3.
// Block: 128 o x 64 px (8x8 half-res tile) for one (b, parity).
// K = 1024 (256c x 4taps) in 8 chunks of 128.
// ---------------------------------------------------------------------------
__global__ __launch_bounds__(256, 2) void convt_wmma(const float* __restrict__ x,
                                                     const float* __restrict__ b1) {
    extern __shared__ __align__(128) char smem[];
    const u32 sb = smem_u32(smem);
    const int tid = threadIdx.x;
    const int wid = tid >> 5;
    const int mo = (wid & 3) * 32;          // warp o offset
    const int np = (wid >> 2) * 32;         // warp px offset

    const int bz = blockIdx.z;              // b*4 + parity
    const int b  = bz >> 2;
    const int par = bz & 3;
    const int di = par >> 1, dj = par & 1;
    const int i0 = blockIdx.y * 8;
    const int j0 = blockIdx.x * 8;
    const int ihBase = i0 + (di == 0 ? -1 : 0);
    const int jwBase = j0 + (dj == 0 ? -1 : 0);

    wmma::fragment<wmma::accumulator, 16, 16, 16, float> acc[2][2];
#pragma unroll
    for (int m = 0; m < 2; m++)
#pragma unroll
        for (int n = 0; n < 2; n++) wmma::fill_fragment(acc[m][n], 0.f);

    const float* xb = x + b * (CIN * H1 * W1);

    for (int kc = 0; kc < 8; kc++) {
        __syncthreads();
        // A: cp.async pre-split weights (rows 256B contiguous -> stride 272B)
        {
            const u32* wAh = g_w1h + (par * 8 + kc) * 8192;
            const u32* wAl = g_w1l + (par * 8 + kc) * 8192;
#pragma unroll
            for (int q = 0; q < 8; q++) {
                int p = tid + q * 256;               // 0..2047 float4 chunks
                int o = p >> 4, ch = p & 15;
                u32 dsto = (u32)(o * (SA * 2) + ch * 16);
                cpasync16(sb + OFF_AH + dsto, wAh + p * 4);
                cpasync16(sb + OFF_AL + dsto, wAl + p * 4);
            }
        }
        // B: x halo, bf16 split. krow = (c-c0)*4 + t*2+u
        const int c0 = kc * 32;
#pragma unroll
        for (int q = 0; q < 16; q++) {
            int p = tid + q * 256;                   // 0..4095 u32 words
            int krow = p >> 5;
            int px0 = (p & 31) * 2;
            int c = c0 + (krow >> 2);
            int t = (krow >> 1) & 1, u = krow & 1;
            int r = px0 >> 3, cw = px0 & 7;
            int h = ihBase + r + t;
            int w = jwBase + cw + u;
            const float* xp = xb + c * (H1 * W1) + h * W1;
            bool okh = (unsigned)h < (unsigned)H1;
            float v0 = (okh && (unsigned)w < (unsigned)W1) ? xp[w] : 0.f;
            float v1 = (okh && (unsigned)(w + 1) < (unsigned)W1) ? xp[w + 1] : 0.f;
            float h0f = __bfloat162float(__float2bfloat16_rn(v0));
            float h1f = __bfloat162float(__float2bfloat16_rn(v1));
            u32 off = (u32)(krow * (SB * 2) + px0 * 2);
            *(u32*)(smem + OFF_BH + off) = pack_bf16x2(v0, v1);
            *(u32*)(smem + OFF_BL + off) = pack_bf16x2(v0 - h0f, v1 - h1f);
        }
        cpasync_wait();
        __syncthreads();

#pragma unroll
        for (int s = 0; s < 3; s++) {
            const __nv_bfloat16* A = (const __nv_bfloat16*)(smem + (s == 2 ? OFF_AL : OFF_AH));
            const __nv_bfloat16* B = (const __nv_bfloat16*)(smem + (s == 1 ? OFF_BL : OFF_BH));
#pragma unroll
            for (int k0 = 0; k0 < 8; k0++) {
                wmma::fragment<wmma::matrix_a, 16, 16, 16, __nv_bfloat16, wmma::row_major> af[2];
                wmma::fragment<wmma::matrix_b, 16, 16, 16, __nv_bfloat16, wmma::row_major> bf[2];
                wmma::load_matrix_sync(af[0], A + mo * SA + k0 * 16, SA);
                wmma::load_matrix_sync(af[1], A + (mo + 16) * SA + k0 * 16, SA);
                wmma::load_matrix_sync(bf[0], B + (k0 * 16) * SB + np, SB);
                wmma::load_matrix_sync(bf[1], B + (k0 * 16) * SB + np + 16, SB);
#pragma unroll
                for (int m = 0; m < 2; m++)
#pragma unroll
                    for (int n = 0; n < 2; n++)
                        wmma::mma_sync(acc[m][n], af[m], bf[n], acc[m][n]);
            }
        }
    }

    // epilogue: fbuf [128][72] fp32, then parity scatter into g_y
    __syncthreads();
    float* fbuf = (float*)smem;
#pragma unroll
    for (int m = 0; m < 2; m++)
#pragma unroll
        for (int n = 0; n < 2; n++)
            wmma::store_matrix_sync(fbuf + (mo + m * 16) * SB + np + n * 16,
                                    acc[m][n], SB, wmma::mem_row_major);
    __syncthreads();
    for (int idx = tid; idx < 8192; idx += 256) {
        int o = idx >> 6;
        int n = idx & 63;
        int r = n >> 3, cw = n & 7;
        float v = fbuf[o * SB + n] + __ldg(&b1[o]);
        g_y[((b * CMID + o) * H2 + 2 * (i0 + r) + di) * W2 + 2 * (j0 + cw) + dj] = v;
    }
}

// ---------------------------------------------------------------------------
// Kernel 2: PAC 3x3 via wmma bf16x3. Block: 128 o x 64 px (8x8 tile).
// 9 ij stages, K=128 each; guide kernel folded into B at staging.
// ---------------------------------------------------------------------------
__global__ __launch_bounds__(256, 2) void pac_wmma(const float* __restrict__ guide,
                                                   const float* __restrict__ b2,
                                                   float* __restrict__ out) {
    extern __shared__ __align__(128) char smem[];
    const u32 sb = smem_u32(smem);
    const int tid = threadIdx.x;
    const int wid = tid >> 5;
    const int mo = (wid & 3) * 32;
    const int np = (wid >> 2) * 32;

    const int b  = blockIdx.z;
    const int h0 = blockIdx.y * 8;
    const int w0 = blockIdx.x * 8;

    float* ks = (float*)(smem + OFF_KS);    // [9][64]
    float* gs = (float*)smem;               // overlay: [32][10][12] = 15360 B

    // ---- Phase A: guide kernel ----
    for (int t = tid; t < 576; t += 256) ks[t] = 0.f;

    for (int cc = 0; cc < CMID; cc += 32) {
        __syncthreads();
        for (int idx = tid; idx < 3200; idx += 256) {
            int c = idx / 100;
            int r = (idx % 100) / 10;
            int col = idx % 10;
            int gh = h0 - 1 + r, gw = w0 - 1 + col;
            float v = 0.f;
            if ((unsigned)gh < (unsigned)H2 && (unsigned)gw < (unsigned)W2)
                v = guide[((b * CMID + cc + c) * H2 + gh) * W2 + gw];
            gs[c * 120 + r * 12 + col] = v;
        }
        __syncthreads();
        for (int idx = tid; idx < 576; idx += 256) {
            int ij = idx >> 6;
            int p  = idx & 63;
            int i = ij / 3, j = ij % 3;
            int r = p >> 3, cw = p & 7;
            float s = 0.f;
#pragma unroll
            for (int c = 0; c < 32; c++) {
                float d = gs[c * 120 + (r + i) * 12 + (cw + j)] - gs[c * 120 + (r + 1) * 12 + (cw + 1)];
                s += d * d;
            }
            ks[idx] += s;
        }
    }
    __syncthreads();
    for (int t = tid; t < 576; t += 256) ks[t] = __expf(-0.5f * ks[t]);

    // ---- Phase B: 9 ij stages ----
    wmma::fragment<wmma::accumulator, 16, 16, 16, float> acc[2][2];
#pragma unroll
    for (int m = 0; m < 2; m++)
#pragma unroll
        for (int n = 0; n < 2; n++) wmma::fill_fragment(acc[m][n], 0.f);

    const float* yb = g_y + b * (CMID * H2 * W2);

    for (int ij = 0; ij < 9; ij++) {
        const int i = ij / 3, j = ij % 3;
        __syncthreads();
        // A: cp.async pre-split weights
        {
            const u32* wAh = g_w2h + ij * 8192;
            const u32* wAl = g_w2l + ij * 8192;
#pragma unroll
            for (int q = 0; q < 8; q++) {
                int p = tid + q * 256;
                int o = p >> 4, ch = p & 15;
                u32 dsto = (u32)(o * (SA * 2) + ch * 16);
                cpasync16(sb + OFF_AH + dsto, wAh + p * 4);
                cpasync16(sb + OFF_AL + dsto, wAl + p * 4);
            }
        }
        // B = y * k, bf16 split
#pragma unroll
        for (int q = 0; q < 16; q++) {
            int p = tid + q * 256;                   // 0..4095
            int c = p >> 5;
            int px0 = (p & 31) * 2;
            int r = px0 >> 3, cw = px0 & 7;
            int h = h0 + r + i - 1;
            int w = w0 + cw + j - 1;
            const float* yp = yb + c * (H2 * W2) + h * W2;
            bool okh = (unsigned)h < (unsigned)H2;
            float v0 = (okh && (unsigned)w < (unsigned)W2) ? yp[w] * ks[ij * 64 + px0] : 0.f;
            float v1 = (okh && (unsigned)(w + 1) < (unsigned)W2) ? yp[w + 1] * ks[ij * 64 + px0 + 1] : 0.f;
            float h0f = __bfloat162float(__float2bfloat16_rn(v0));
            float h1f = __bfloat162float(__float2bfloat16_rn(v1));
            u32 off = (u32)(c * (SB * 2) + px0 * 2);
            *(u32*)(smem + OFF_BH + off) = pack_bf16x2(v0, v1);
            *(u32*)(smem + OFF_BL + off) = pack_bf16x2(v0 - h0f, v1 - h1f);
        }
        cpasync_wait();
        __syncthreads();

#pragma unroll
        for (int s = 0; s < 3; s++) {
            const __nv_bfloat16* A = (const __nv_bfloat16*)(smem + (s == 2 ? OFF_AL : OFF_AH));
            const __nv_bfloat16* B = (const __nv_bfloat16*)(smem + (s == 1 ? OFF_BL : OFF_BH));
#pragma unroll
            for (int k0 = 0; k0 < 8; k0++) {
                wmma::fragment<wmma::matrix_a, 16, 16, 16, __nv_bfloat16, wmma::row_major> af[2];
                wmma::fragment<wmma::matrix_b, 16, 16, 16, __nv_bfloat16, wmma::row_major> bf[2];
                wmma::load_matrix_sync(af[0], A + mo * SA + k0 * 16, SA);
                wmma::load_matrix_sync(af[1], A + (mo + 16) * SA + k0 * 16, SA);
                wmma::load_matrix_sync(bf[0], B + (k0 * 16) * SB + np, SB);
                wmma::load_matrix_sync(bf[1], B + (k0 * 16) * SB + np + 16, SB);
#pragma unroll
                for (int m = 0; m < 2; m++)
#pragma unroll
                    for (int n = 0; n < 2; n++)
                        wmma::mma_sync(acc[m][n], af[m], bf[n], acc[m][n]);
            }
        }
    }

    // ---- Epilogue ----
    __syncthreads();
    float* fbuf = (float*)smem;              // [128][72]
#pragma unroll
    for (int m = 0; m < 2; m++)
#pragma unroll
        for (int n = 0; n < 2; n++)
            wmma::store_matrix_sync(fbuf + (mo + m * 16) * SB + np + n * 16,
                                    acc[m][n], SB, wmma::mem_row_major);
    __syncthreads();
    for (int idx = tid; idx < 8192; idx += 256) {
        int o = idx >> 6;
        int n = idx & 63;
        float v = fbuf[o * SB + n] + __ldg(&b2[o]);
        out[((b * CMID + o) * H2 + h0 + (n >> 3)) * W2 + w0 + (n & 7)] = v;
    }
}

extern "C" void kernel_launch(void* const* d_in, const int* in_sizes, int n_in,
                              void* d_out, int out_size) {
    const float* x     = (const float*)d_in[0];
    const float* guide = (const float*)d_in[1];
    const float* w1    = (const float*)d_in[2];
    const float* b1    = (const float*)d_in[3];
    const float* w2    = (const float*)d_in[4];
    const float* b2    = (const float*)d_in[5];
    float* out = (float*)d_out;

    cudaFuncSetAttribute(convt_wmma, cudaFuncAttributeMaxDynamicSharedMemorySize, CONVT_SMEM);
    cudaFuncSetAttribute(pac_wmma, cudaFuncAttributeMaxDynamicSharedMemorySize, PAC_SMEM);

    split_w1<<<(4 * 8 * 128 * 64 + 255) / 256, 256>>>(w1);
    split_w2<<<(9 * 128 * 64 + 255) / 256, 256>>>(w2);
    convt_wmma<<<dim3(8, 8, BATCH * 4), 256, CONVT_SMEM>>>(x, b1);
    pac_wmma<<<dim3(16, 16, BATCH), 256, PAC_SMEM>>>(guide, b2, out);
}

// round 7
// speedup vs baseline: 2.3274x; 1.9718x over previous
#include <cuda_runtime.h>
#include <cuda_fp16.h>
#include <mma.h>
#include <cstdint>

// UpConvBlock: y = ConvTranspose2d(x, w1, k=4, s=2, p=1) + b1
//              out = PAC-3x3(y, guide, w2) + b2
// R7: both stages as fp16 HMMA GEMMs with SPLIT WEIGHTS (A = Ah + Al, exact
// to 2^-24) and single-fp16 activations (B). 2 MMA products per k-step.
// K chunked by 64 -> 48.4KB smem -> 3 CTAs/SM.

#define H1 64
#define W1 64
#define CIN 256
#define CMID 128
#define H2 128
#define W2 128
#define BATCH 4

typedef unsigned long long u64;
typedef unsigned int u32;

using namespace nvcuda;

__device__ __forceinline__ u32 pack_f16x2(float lo, float hi) {
    u32 r; asm("cvt.rn.f16x2.f32 %0, %1, %2;" : "=r"(r) : "f"(hi), "f"(lo)); return r;
}
__device__ __forceinline__ u32 smem_u32(const void* p) {
    u32 a; asm("{ .reg .u64 t; cvta.to.shared.u64 t, %1; cvt.u32.u64 %0, t; }" : "=r"(a) : "l"(p));
    return a;
}
__device__ __forceinline__ void cpasync16(u32 dst, const void* src) {
    asm volatile("cp.async.ca.shared.global [%0], [%1], 16;" :: "r"(dst), "l"(src));
}
__device__ __forceinline__ void cpasync_wait() {
    asm volatile("cp.async.commit_group;\n\tcp.async.wait_group 0;" ::: "memory");
}

// ---------------- scratch globals ----------------
__device__ float g_y[BATCH * CMID * H2 * W2];
__device__ __align__(128) __half g_w1h[4 * 16 * 128 * 64];   // [par][kc][o][krow]
__device__ __align__(128) __half g_w1l[4 * 16 * 128 * 64];
__device__ __align__(128) __half g_w2h[9 * 2 * 128 * 64];    // [ij][kc][o][c]
__device__ __align__(128) __half g_w2l[9 * 2 * 128 * 64];

// smem layout: A rows (128) stride 72 halves; B rows (64) stride 72 halves
#define SA 72
#define SB 72
#define OFF_AH 0
#define OFF_AL 18432
#define OFF_B  36864
#define OFF_KS 46080                     // pac only: fp32 [9][64]
#define CONVT_SMEM 46080
#define PAC_SMEM   48384

// ---------------------------------------------------------------------------
// Weight pre-split kernels (fp16 hi/lo)
// ---------------------------------------------------------------------------
__global__ void split_w1(const float* __restrict__ w1) {
    int idx = blockIdx.x * 256 + threadIdx.x;        // 4*16*128*64 = 524288
    if (idx >= 4 * 16 * 128 * 64) return;
    int kr = idx & 63;
    int o  = (idx >> 6) & 127;
    int kc = (idx >> 13) & 15;
    int par = idx >> 17;
    int di = par >> 1, dj = par & 1;
    int c = kc * 16 + (kr >> 2);
    int tap = kr & 3;
    int t = tap >> 1, u = tap & 1;
    float v = w1[(c * CMID + o) * 16 + (3 - di - 2 * t) * 4 + (3 - dj - 2 * u)];
    __half h = __float2half_rn(v);
    g_w1h[idx] = h;
    g_w1l[idx] = __float2half_rn(v - __half2float(h));
}

__global__ void split_w2(const float* __restrict__ w2) {
    int idx = blockIdx.x * 256 + threadIdx.x;        // 9*2*128*64 = 147456
    if (idx >= 9 * 2 * 128 * 64) return;
    int ck = idx & 63;
    int o  = (idx >> 6) & 127;
    int kc = (idx >> 13) & 1;
    int ij = idx >> 14;
    int i = ij / 3, j = ij % 3;
    int c = kc * 64 + ck;
    float v = w2[(c * CMID + o) * 9 + (2 - i) * 3 + (2 - j)];
    __half h = __float2half_rn(v);
    g_w2h[idx] = h;
    g_w2l[idx] = __float2half_rn(v - __half2float(h));
}

// ---------------------------------------------------------------------------
// Shared MMA stage: A[128][64] (hi+lo in smem), B[64][64], 2 products.
// ---------------------------------------------------------------------------
template<typename AccT>
__device__ __forceinline__ void mma_stage(const char* smem, int mo, int np, AccT (&acc)[2][2]) {
#pragma unroll
    for (int k0 = 0; k0 < 4; k0++) {
        wmma::fragment<wmma::matrix_b, 16, 16, 16, __half, wmma::row_major> bf[2];
        const __half* B = (const __half*)(smem + OFF_B);
        wmma::load_matrix_sync(bf[0], B + (k0 * 16) * SB + np, SB);
        wmma::load_matrix_sync(bf[1], B + (k0 * 16) * SB + np + 16, SB);
#pragma unroll
        for (int s = 0; s < 2; s++) {
            const __half* A = (const __half*)(smem + (s ? OFF_AL : OFF_AH));
            wmma::fragment<wmma::matrix_a, 16, 16, 16, __half, wmma::row_major> af[2];
            wmma::load_matrix_sync(af[0], A + mo * SA + k0 * 16, SA);
            wmma::load_matrix_sync(af[1], A + (mo + 16) * SA + k0 * 16, SA);
#pragma unroll
            for (int m = 0; m < 2; m++)
#pragma unroll
                for (int n = 0; n < 2; n++)
                    wmma::mma_sync(acc[m][n], af[m], bf[n], acc[m][n]);
        }
    }
}

// ---------------------------------------------------------------------------
// Kernel 1: conv_transpose via parity decomposition. Block: 128o x 64px.
// K = 1024 in 16 chunks of 64 (16c x 4taps each).
// ---------------------------------------------------------------------------
__global__ __launch_bounds__(256, 3) void convt_wmma(const float* __restrict__ x,
                                                     const float* __restrict__ b1) {
    extern __shared__ __align__(128) char smem[];
    const u32 sb = smem_u32(smem);
    const int tid = threadIdx.x;
    const int wid = tid >> 5;
    const int mo = (wid & 3) * 32;
    const int np = (wid >> 2) * 32;

    const int bz = blockIdx.z;
    const int b  = bz >> 2;
    const int par = bz & 3;
    const int di = par >> 1, dj = par & 1;
    const int i0 = blockIdx.y * 8;
    const int j0 = blockIdx.x * 8;
    const int ihBase = i0 + (di == 0 ? -1 : 0);
    const int jwBase = j0 + (dj == 0 ? -1 : 0);

    wmma::fragment<wmma::accumulator, 16, 16, 16, float> acc[2][2];
#pragma unroll
    for (int m = 0; m < 2; m++)
#pragma unroll
        for (int n = 0; n < 2; n++) wmma::fill_fragment(acc[m][n], 0.f);

    const float* xb = x + b * (CIN * H1 * W1);

    for (int kc = 0; kc < 16; kc++) {
        __syncthreads();
        // A: cp.async pre-split fp16 weights (row = 64 halves = 128B)
        {
            const __half* wAh = g_w1h + (par * 16 + kc) * 8192;
            const __half* wAl = g_w1l + (par * 16 + kc) * 8192;
#pragma unroll
            for (int q = 0; q < 4; q++) {
                int p = tid + q * 256;               // 0..1023
                int o = p >> 3, ch = p & 7;
                u32 dsto = (u32)(o * (SA * 2) + ch * 16);
                cpasync16(sb + OFF_AH + dsto, wAh + o * 64 + ch * 8);
                cpasync16(sb + OFF_AL + dsto, wAl + o * 64 + ch * 8);
            }
        }
        // B: x halo, single fp16. krow = c_local*4 + t*2 + u
        const int c0 = kc * 16;
#pragma unroll
        for (int q = 0; q < 8; q++) {
            int p = tid + q * 256;                   // 0..2047 u32 words
            int krow = p >> 5;
            int px0 = (p & 31) * 2;
            int c = c0 + (krow >> 2);
            int t = (krow >> 1) & 1, u = krow & 1;
            int r = px0 >> 3, cw = px0 & 7;
            int h = ihBase + r + t;
            int w = jwBase + cw + u;
            const float* xp = xb + c * (H1 * W1) + h * W1;
            bool okh = (unsigned)h < (unsigned)H1;
            float v0 = (okh && (unsigned)w < (unsigned)W1) ? xp[w] : 0.f;
            float v1 = (okh && (unsigned)(w + 1) < (unsigned)W1) ? xp[w + 1] : 0.f;
            *(u32*)(smem + OFF_B + krow * (SB * 2) + px0 * 2) = pack_f16x2(v0, v1);
        }
        cpasync_wait();
        __syncthreads();

        mma_stage(smem, mo, np, acc);
    }

    // epilogue: fbuf [128][72] fp32 (overlays A), parity scatter into g_y
    __syncthreads();
    float* fbuf = (float*)smem;
#pragma unroll
    for (int m = 0; m < 2; m++)
#pragma unroll
        for (int n = 0; n < 2; n++)
            wmma::store_matrix_sync(fbuf + (mo + m * 16) * SB + np + n * 16,
                                    acc[m][n], SB, wmma::mem_row_major);
    __syncthreads();
    for (int idx = tid; idx < 8192; idx += 256) {
        int o = idx >> 6;
        int n = idx & 63;
        int r = n >> 3, cw = n & 7;
        float v = fbuf[o * SB + n] + __ldg(&b1[o]);
        g_y[((b * CMID + o) * H2 + 2 * (i0 + r) + di) * W2 + 2 * (j0 + cw) + dj] = v;
    }
}

// ---------------------------------------------------------------------------
// Kernel 2: PAC 3x3. Block: 128o x 64px (8x8 tile). 2 kc chunks x 9 ij stages.
// ---------------------------------------------------------------------------
__global__ __launch_bounds__(256, 3) void pac_wmma(const float* __restrict__ guide,
                                                   const float* __restrict__ b2,
                                                   float* __restrict__ out) {
    extern __shared__ __align__(128) char smem[];
    const u32 sb = smem_u32(smem);
    const int tid = threadIdx.x;
    const int wid = tid >> 5;
    const int mo = (wid & 3) * 32;
    const int np = (wid >> 2) * 32;

    const int b  = blockIdx.z;
    const int h0 = blockIdx.y * 8;
    const int w0 = blockIdx.x * 8;

    float* ks = (float*)(smem + OFF_KS);    // [9][64]
    float* gs = (float*)smem;               // overlay: [32][10][12]

    // ---- Phase A: guide kernel ----
    for (int t = tid; t < 576; t += 256) ks[t] = 0.f;

    for (int cc = 0; cc < CMID; cc += 32) {
        __syncthreads();
        for (int idx = tid; idx < 3200; idx += 256) {
            int c = idx / 100;
            int r = (idx % 100) / 10;
            int col = idx % 10;
            int gh = h0 - 1 + r, gw = w0 - 1 + col;
            float v = 0.f;
            if ((unsigned)gh < (unsigned)H2 && (unsigned)gw < (unsigned)W2)
                v = guide[((b * CMID + cc + c) * H2 + gh) * W2 + gw];
            gs[c * 120 + r * 12 + col] = v;
        }
        __syncthreads();
        for (int idx = tid; idx < 576; idx += 256) {
            int ij = idx >> 6;
            int p  = idx & 63;
            int i = ij / 3, j = ij % 3;
            int r = p >> 3, cw = p & 7;
            float s = 0.f;
#pragma unroll
            for (int c = 0; c < 32; c++) {
                float d = gs[c * 120 + (r + i) * 12 + (cw + j)] - gs[c * 120 + (r + 1) * 12 + (cw + 1)];
                s += d * d;
            }
            ks[idx] += s;
        }
    }
    __syncthreads();
    for (int t = tid; t < 576; t += 256) ks[t] = __expf(-0.5f * ks[t]);

    // ---- Phase B: 2 kc x 9 ij stages ----
    wmma::fragment<wmma::accumulator, 16, 16, 16, float> acc[2][2];
#pragma unroll
    for (int m = 0; m < 2; m++)
#pragma unroll
        for (int n = 0; n < 2; n++) wmma::fill_fragment(acc[m][n], 0.f);

    const float* yb = g_y + b * (CMID * H2 * W2);

    for (int kc = 0; kc < 2; kc++) {
        for (int ij = 0; ij < 9; ij++) {
            const int i = ij / 3, j = ij % 3;
            __syncthreads();
            // A: cp.async pre-split fp16 weights
            {
                const __half* wAh = g_w2h + (ij * 2 + kc) * 8192;
                const __half* wAl = g_w2l + (ij * 2 + kc) * 8192;
#pragma unroll
                for (int q = 0; q < 4; q++) {
                    int p = tid + q * 256;
                    int o = p >> 3, ch = p & 7;
                    u32 dsto = (u32)(o * (SA * 2) + ch * 16);
                    cpasync16(sb + OFF_AH + dsto, wAh + o * 64 + ch * 8);
                    cpasync16(sb + OFF_AL + dsto, wAl + o * 64 + ch * 8);
                }
            }
            // B = y * k, single fp16
            const int c0 = kc * 64;
#pragma unroll
            for (int q = 0; q < 8; q++) {
                int p = tid + q * 256;               // 0..2047
                int c = c0 + (p >> 5);
                int px0 = (p & 31) * 2;
                int r = px0 >> 3, cw = px0 & 7;
                int h = h0 + r + i - 1;
                int w = w0 + cw + j - 1;
                const float* yp = yb + c * (H2 * W2) + h * W2;
                bool okh = (unsigned)h < (unsigned)H2;
                float v0 = (okh && (unsigned)w < (unsigned)W2) ? yp[w] * ks[ij * 64 + px0] : 0.f;
                float v1 = (okh && (unsigned)(w + 1) < (unsigned)W2) ? yp[w + 1] * ks[ij * 64 + px0 + 1] : 0.f;
                *(u32*)(smem + OFF_B + (p >> 5) * (SB * 2) + px0 * 2) = pack_f16x2(v0, v1);
            }
            cpasync_wait();
            __syncthreads();

            mma_stage(smem, mo, np, acc);
        }
    }

    // ---- Epilogue ----
    __syncthreads();
    float* fbuf = (float*)smem;              // [128][72]
#pragma unroll
    for (int m = 0; m < 2; m++)
#pragma unroll
        for (int n = 0; n < 2; n++)
            wmma::store_matrix_sync(fbuf + (mo + m * 16) * SB + np + n * 16,
                                    acc[m][n], SB, wmma::mem_row_major);
    __syncthreads();
    for (int idx = tid; idx < 8192; idx += 256) {
        int o = idx >> 6;
        int n = idx & 63;
        float v = fbuf[o * SB + n] + __ldg(&b2[o]);
        out[((b * CMID + o) * H2 + h0 + (n >> 3)) * W2 + w0 + (n & 7)] = v;
    }
}

extern "C" void kernel_launch(void* const* d_in, const int* in_sizes, int n_in,
                              void* d_out, int out_size) {
    const float* x     = (const float*)d_in[0];
    const float* guide = (const float*)d_in[1];
    const float* w1    = (const float*)d_in[2];
    const float* b1    = (const float*)d_in[3];
    const float* w2    = (const float*)d_in[4];
    const float* b2    = (const float*)d_in[5];
    float* out = (float*)d_out;

    cudaFuncSetAttribute(convt_wmma, cudaFuncAttributeMaxDynamicSharedMemorySize, CONVT_SMEM);
    cudaFuncSetAttribute(pac_wmma, cudaFuncAttributeMaxDynamicSharedMemorySize, PAC_SMEM);

    split_w1<<<(4 * 16 * 128 * 64 + 255) / 256, 256>>>(w1);
    split_w2<<<(9 * 2 * 128 * 64 + 255) / 256, 256>>>(w2);
    convt_wmma<<<dim3(8, 8, BATCH * 4), 256, CONVT_SMEM>>>(x, b1);
    pac_wmma<<<dim3(16, 16, BATCH), 256, PAC_SMEM>>>(guide, b2, out);
}